// round 7
// baseline (speedup 1.0000x reference)
#include <cuda_runtime.h>
#include <cuda_bf16.h>
#include <cstdint>

#define NFEAT  6
#define D      256
#define NPAIRS 15
#define BM     32
#define TPB    128
#define KC     16            // k-rows per pipelined chunk
#define NC     (D / KC)      // 16 chunks per 256-K GEMM

// triu_indices(6, k=1) pair order
__device__ __constant__ int cPI[NPAIRS] = {0,0,0,0,0,1,1,1,1,2,2,2,3,3,4};
__device__ __constant__ int cPJ[NPAIRS] = {1,2,3,4,5,2,3,4,5,3,4,5,4,5,5};

__device__ __forceinline__ void cp16(float* s, const float* g)
{
    unsigned int sa = (unsigned int)__cvta_generic_to_shared(s);
    asm volatile("cp.async.cg.shared.global [%0], [%1], 16;" :: "r"(sa), "l"(g));
}
#define CP_COMMIT() asm volatile("cp.async.commit_group;")
#define CP_WAIT0()  asm volatile("cp.async.wait_group 0;")

// One 256-K GEMM: acc[8][8] += Asm[32][256] @ wg[256][256].
// cp.async double-buffered over 16-row W chunks; optionally stages Asm from
// gmem (ag) inside the first cp.async group.
// Thread tile: rows mr0..mr0+7 (warp-broadcast A reads),
// cols lane*4..+3 and 128+lane*4..+3 (warp B read = 512B contiguous, no
// bank conflicts).
__device__ __forceinline__ void gemm_stage(const float* __restrict__ Asm,
                                           const float* __restrict__ wg,
                                           float*       __restrict__ sWbuf,
                                           float acc[8][8],
                                           int tid, int mr0, int lane,
                                           const float* __restrict__ ag)
{
    __syncthreads();                       // all warps done with prior sA/sW/sH use
    if (ag) {                              // stage A tile (32KB contiguous)
#pragma unroll
        for (int r = 0; r < 16; r++)
            cp16((float*)Asm + 4 * (tid + r * TPB), ag + 4 * (tid + r * TPB));
    }
#pragma unroll
    for (int r = 0; r < 8; r++)            // W chunk 0 -> buf0 (16KB)
        cp16(sWbuf + 4 * (tid + r * TPB), wg + 4 * (tid + r * TPB));
    CP_COMMIT();

#pragma unroll 1
    for (int kc = 0; kc < NC; kc++) {
        CP_WAIT0();
        __syncthreads();                   // chunk kc (and A) visible to all
        if (kc + 1 < NC) {                 // prefetch chunk kc+1, overlaps mma
            float*       nb = sWbuf + ((kc + 1) & 1) * (KC * D);
            const float* ng = wg + (size_t)(kc + 1) * KC * D;
#pragma unroll
            for (int r = 0; r < 8; r++)
                cp16(nb + 4 * (tid + r * TPB), ng + 4 * (tid + r * TPB));
            CP_COMMIT();
        }
        const float* Wc = sWbuf + (kc & 1) * (KC * D);
        const int kb = kc * KC;
#pragma unroll
        for (int kk = 0; kk < KC; kk += 4) {
            float a[8][4];
#pragma unroll
            for (int i = 0; i < 8; i++) {  // warp-broadcast (1-cyc) A reads
                float4 t = *(const float4*)(Asm + (mr0 + i) * D + kb + kk);
                a[i][0] = t.x; a[i][1] = t.y; a[i][2] = t.z; a[i][3] = t.w;
            }
#pragma unroll
            for (int kj = 0; kj < 4; kj++) {
                float4 b0 = *(const float4*)(Wc + (kk + kj) * D + lane * 4);
                float4 b1 = *(const float4*)(Wc + (kk + kj) * D + 128 + lane * 4);
                float bb[8] = {b0.x, b0.y, b0.z, b0.w, b1.x, b1.y, b1.z, b1.w};
#pragma unroll
                for (int i = 0; i < 8; i++)
#pragma unroll
                    for (int j = 0; j < 8; j++)
                        acc[i][j] = fmaf(a[i][kj], bb[j], acc[i][j]);
            }
        }
    }
}

__global__ void __launch_bounds__(TPB, 2)
cblock_kernel(const float* __restrict__ features,  // [6][M][256]
              const float* __restrict__ W_pair,    // [15][512][256]
              const float* __restrict__ b_pair,    // [15][256]
              const float* __restrict__ W_final,   // [3840][256]
              const float* __restrict__ b_final,   // [256]
              const int*   __restrict__ NAS,       // [6]
              float*       __restrict__ out,       // [M][256]
              int M)
{
    extern __shared__ float smem[];
    float* sA = smem;                     // 32 x 256   (feature tile, 32KB)
    float* sW = smem + BM * D;            // 2 x 16x256 (double-buffered W, 32KB)
    float* sH = smem + 2 * BM * D;        // 32 x 256   (tanh activations, 32KB)
    __shared__ float sMask[NPAIRS];
    __shared__ int   sNas[NFEAT];

    const int tid  = threadIdx.x;
    const int lane = tid & 31;
    const int wid  = tid >> 5;            // 4 warps, each owns 8 rows
    const int mr0  = wid * 8;
    const int c0   = lane * 4;            // first column group
    const int c1   = 128 + lane * 4;      // second column group
    const size_t m0 = (size_t)blockIdx.x * BM;

    if (tid < NFEAT) { int v = NAS[tid]; if (tid < 2) v = 1; sNas[tid] = v; }
    __syncthreads();
    if (tid < NPAIRS) sMask[tid] = (float)(sNas[cPI[tid]] * sNas[cPJ[tid]]);
    __syncthreads();

    // out accumulator, init with b_final
    float oacc[8][8];
    {
        float4 f0 = *(const float4*)(b_final + c0);
        float4 f1 = *(const float4*)(b_final + c1);
#pragma unroll
        for (int i = 0; i < 8; i++) {
            oacc[i][0] = f0.x; oacc[i][1] = f0.y; oacc[i][2] = f0.z; oacc[i][3] = f0.w;
            oacc[i][4] = f1.x; oacc[i][5] = f1.y; oacc[i][6] = f1.z; oacc[i][7] = f1.w;
        }
    }

#pragma unroll 1
    for (int p = 0; p < NPAIRS; p++) {
        if (sMask[p] == 0.0f) continue;   // exact: masked pair contributes zero

        // h accumulator, init with b_pair[p]
        float hacc[8][8];
        {
            float4 b0 = *(const float4*)(b_pair + p * D + c0);
            float4 b1 = *(const float4*)(b_pair + p * D + c1);
#pragma unroll
            for (int i = 0; i < 8; i++) {
                hacc[i][0] = b0.x; hacc[i][1] = b0.y; hacc[i][2] = b0.z; hacc[i][3] = b0.w;
                hacc[i][4] = b1.x; hacc[i][5] = b1.y; hacc[i][6] = b1.z; hacc[i][7] = b1.w;
            }
        }

        // Stage 1: hacc += f_i @ W_top  +  f_j @ W_bot
        {
            const int fi = cPI[p], fj = cPJ[p];
            gemm_stage(sA, W_pair + (size_t)p * 2 * D * D, sW, hacc,
                       tid, mr0, lane, features + ((size_t)fi * M + m0) * D);
            gemm_stage(sA, W_pair + ((size_t)p * 2 * D + D) * D, sW, hacc,
                       tid, mr0, lane, features + ((size_t)fj * M + m0) * D);
        }

        // tanh -> sH (stage2's internal barriers order writes before reads)
#pragma unroll
        for (int i = 0; i < 8; i++) {
            float4 v0, v1;
            v0.x = tanhf(hacc[i][0]); v0.y = tanhf(hacc[i][1]);
            v0.z = tanhf(hacc[i][2]); v0.w = tanhf(hacc[i][3]);
            v1.x = tanhf(hacc[i][4]); v1.y = tanhf(hacc[i][5]);
            v1.z = tanhf(hacc[i][6]); v1.w = tanhf(hacc[i][7]);
            *(float4*)(sH + (mr0 + i) * D + c0) = v0;
            *(float4*)(sH + (mr0 + i) * D + c1) = v1;
        }

        // Stage 2: oacc += sH @ W_final[p*256:(p+1)*256, :]
        gemm_stage(sH, W_final + (size_t)p * D * D, sW, oacc,
                   tid, mr0, lane, (const float*)0);
    }

    // epilogue: coalesced float4 stores
    float* orow = out + m0 * D;
#pragma unroll
    for (int i = 0; i < 8; i++) {
        float4 v0, v1;
        v0.x = oacc[i][0]; v0.y = oacc[i][1]; v0.z = oacc[i][2]; v0.w = oacc[i][3];
        v1.x = oacc[i][4]; v1.y = oacc[i][5]; v1.z = oacc[i][6]; v1.w = oacc[i][7];
        *(float4*)(orow + (mr0 + i) * D + c0) = v0;
        *(float4*)(orow + (mr0 + i) * D + c1) = v1;
    }
}

extern "C" void kernel_launch(void* const* d_in, const int* in_sizes, int n_in,
                              void* d_out, int out_size)
{
    const float* features = (const float*)d_in[0];
    const float* W_pair   = (const float*)d_in[1];
    const float* b_pair   = (const float*)d_in[2];
    const float* W_final  = (const float*)d_in[3];
    const float* b_final  = (const float*)d_in[4];
    const int*   NAS      = (const int*)d_in[5];
    float*       out      = (float*)d_out;

    const int M = in_sizes[0] / (NFEAT * D);      // 16384 tokens
    const int grid = M / BM;                      // 512 blocks
    const size_t smem_bytes = 3 * (size_t)BM * D * sizeof(float);   // 96 KB

    cudaFuncSetAttribute(cblock_kernel,
                         cudaFuncAttributeMaxDynamicSharedMemorySize,
                         (int)smem_bytes);
    cblock_kernel<<<grid, TPB, smem_bytes>>>(features, W_pair, b_pair,
                                             W_final, b_final, NAS, out, M);
}

// round 8
// speedup vs baseline: 1.0527x; 1.0527x over previous
#include <cuda_runtime.h>
#include <cuda_bf16.h>
#include <cstdint>

#define NFEAT  6
#define D      256
#define NPAIRS 15
#define BM     64            // M-tile: doubled to halve L2 weight traffic
#define TPB    256
#define KC     16            // k-rows per pipelined chunk
#define NC     (D / KC)      // 16 chunks per 256-K GEMM

// triu_indices(6, k=1) pair order
__device__ __constant__ int cPI[NPAIRS] = {0,0,0,0,0,1,1,1,1,2,2,2,3,3,4};
__device__ __constant__ int cPJ[NPAIRS] = {1,2,3,4,5,2,3,4,5,3,4,5,4,5,5};

__device__ __forceinline__ void cp16(float* s, const float* g)
{
    unsigned int sa = (unsigned int)__cvta_generic_to_shared(s);
    asm volatile("cp.async.cg.shared.global [%0], [%1], 16;" :: "r"(sa), "l"(g));
}
#define CP_COMMIT() asm volatile("cp.async.commit_group;")
#define CP_WAIT0()  asm volatile("cp.async.wait_group 0;")

// One 256-K GEMM: acc[8][8] += Asm[64][256] @ wg[256][256].
// cp.async double-buffered over 16-row W chunks; optionally stages Asm from
// gmem (ag) inside the first cp.async group.
// Thread tile: rows mr0..mr0+7 (warp-broadcast A reads),
// cols lane*4..+3 and 128+lane*4..+3 (warp B read = 512B contiguous,
// conflict-free LDS.128).
__device__ __forceinline__ void gemm_stage(const float* __restrict__ Asm,
                                           const float* __restrict__ wg,
                                           float*       __restrict__ sWbuf,
                                           float acc[8][8],
                                           int tid, int mr0, int lane,
                                           const float* __restrict__ ag)
{
    __syncthreads();                       // all warps done with prior sA/sW/sH use
    if (ag) {                              // stage A tile (64KB contiguous)
#pragma unroll
        for (int r = 0; r < 16; r++)
            cp16((float*)Asm + 4 * (tid + r * TPB), ag + 4 * (tid + r * TPB));
    }
#pragma unroll
    for (int r = 0; r < 4; r++)            // W chunk 0 -> buf0 (16KB)
        cp16(sWbuf + 4 * (tid + r * TPB), wg + 4 * (tid + r * TPB));
    CP_COMMIT();

#pragma unroll 1
    for (int kc = 0; kc < NC; kc++) {
        CP_WAIT0();
        __syncthreads();                   // chunk kc (and A) visible; prev compute done
        if (kc + 1 < NC) {                 // prefetch chunk kc+1, overlaps mma
            float*       nb = sWbuf + ((kc + 1) & 1) * (KC * D);
            const float* ng = wg + (size_t)(kc + 1) * KC * D;
#pragma unroll
            for (int r = 0; r < 4; r++)
                cp16(nb + 4 * (tid + r * TPB), ng + 4 * (tid + r * TPB));
            CP_COMMIT();
        }
        const float* Wc = sWbuf + (kc & 1) * (KC * D);
        const int kb = kc * KC;
#pragma unroll
        for (int kk = 0; kk < KC; kk += 4) {
            float a[8][4];
#pragma unroll
            for (int i = 0; i < 8; i++) {  // warp-broadcast (1-cyc) A reads
                float4 t = *(const float4*)(Asm + (mr0 + i) * D + kb + kk);
                a[i][0] = t.x; a[i][1] = t.y; a[i][2] = t.z; a[i][3] = t.w;
            }
#pragma unroll
            for (int kj = 0; kj < 4; kj++) {
                float4 b0 = *(const float4*)(Wc + (kk + kj) * D + lane * 4);
                float4 b1 = *(const float4*)(Wc + (kk + kj) * D + 128 + lane * 4);
                float bb[8] = {b0.x, b0.y, b0.z, b0.w, b1.x, b1.y, b1.z, b1.w};
#pragma unroll
                for (int i = 0; i < 8; i++)
#pragma unroll
                    for (int j = 0; j < 8; j++)
                        acc[i][j] = fmaf(a[i][kj], bb[j], acc[i][j]);
            }
        }
    }
}

__global__ void __launch_bounds__(TPB, 1)
cblock_kernel(const float* __restrict__ features,  // [6][M][256]
              const float* __restrict__ W_pair,    // [15][512][256]
              const float* __restrict__ b_pair,    // [15][256]
              const float* __restrict__ W_final,   // [3840][256]
              const float* __restrict__ b_final,   // [256]
              const int*   __restrict__ NAS,       // [6]
              float*       __restrict__ out,       // [M][256]
              int M)
{
    extern __shared__ float smem[];
    float* sA = smem;                     // 64 x 256   (feature tile, 64KB)
    float* sW = smem + BM * D;            // 2 x 16x256 (double-buffered W, 32KB)
    float* sH = smem + BM * D + 2 * KC * D; // 64 x 256  (tanh activations, 64KB)
    __shared__ float sMask[NPAIRS];
    __shared__ int   sNas[NFEAT];

    const int tid  = threadIdx.x;
    const int lane = tid & 31;
    const int wid  = tid >> 5;            // 8 warps, each owns 8 rows
    const int mr0  = wid * 8;
    const int c0   = lane * 4;            // first column group
    const int c1   = 128 + lane * 4;      // second column group
    const size_t m0 = (size_t)blockIdx.x * BM;

    if (tid < NFEAT) { int v = NAS[tid]; if (tid < 2) v = 1; sNas[tid] = v; }
    __syncthreads();
    if (tid < NPAIRS) sMask[tid] = (float)(sNas[cPI[tid]] * sNas[cPJ[tid]]);
    __syncthreads();

    // out accumulator, init with b_final
    float oacc[8][8];
    {
        float4 f0 = *(const float4*)(b_final + c0);
        float4 f1 = *(const float4*)(b_final + c1);
#pragma unroll
        for (int i = 0; i < 8; i++) {
            oacc[i][0] = f0.x; oacc[i][1] = f0.y; oacc[i][2] = f0.z; oacc[i][3] = f0.w;
            oacc[i][4] = f1.x; oacc[i][5] = f1.y; oacc[i][6] = f1.z; oacc[i][7] = f1.w;
        }
    }

#pragma unroll 1
    for (int p = 0; p < NPAIRS; p++) {
        if (sMask[p] == 0.0f) continue;   // exact: masked pair contributes zero

        // h accumulator, init with b_pair[p]
        float hacc[8][8];
        {
            float4 b0 = *(const float4*)(b_pair + p * D + c0);
            float4 b1 = *(const float4*)(b_pair + p * D + c1);
#pragma unroll
            for (int i = 0; i < 8; i++) {
                hacc[i][0] = b0.x; hacc[i][1] = b0.y; hacc[i][2] = b0.z; hacc[i][3] = b0.w;
                hacc[i][4] = b1.x; hacc[i][5] = b1.y; hacc[i][6] = b1.z; hacc[i][7] = b1.w;
            }
        }

        // Stage 1: hacc += f_i @ W_top  +  f_j @ W_bot
        {
            const int fi = cPI[p], fj = cPJ[p];
            gemm_stage(sA, W_pair + (size_t)p * 2 * D * D, sW, hacc,
                       tid, mr0, lane, features + ((size_t)fi * M + m0) * D);
            gemm_stage(sA, W_pair + ((size_t)p * 2 * D + D) * D, sW, hacc,
                       tid, mr0, lane, features + ((size_t)fj * M + m0) * D);
        }

        // tanh -> sH (stage2's internal barriers order writes before reads)
#pragma unroll
        for (int i = 0; i < 8; i++) {
            float4 v0, v1;
            v0.x = tanhf(hacc[i][0]); v0.y = tanhf(hacc[i][1]);
            v0.z = tanhf(hacc[i][2]); v0.w = tanhf(hacc[i][3]);
            v1.x = tanhf(hacc[i][4]); v1.y = tanhf(hacc[i][5]);
            v1.z = tanhf(hacc[i][6]); v1.w = tanhf(hacc[i][7]);
            *(float4*)(sH + (mr0 + i) * D + c0) = v0;
            *(float4*)(sH + (mr0 + i) * D + c1) = v1;
        }

        // Stage 2: oacc += sH @ W_final[p*256:(p+1)*256, :]
        gemm_stage(sH, W_final + (size_t)p * D * D, sW, oacc,
                   tid, mr0, lane, (const float*)0);
    }

    // epilogue: coalesced float4 stores
    float* orow = out + m0 * D;
#pragma unroll
    for (int i = 0; i < 8; i++) {
        float4 v0, v1;
        v0.x = oacc[i][0]; v0.y = oacc[i][1]; v0.z = oacc[i][2]; v0.w = oacc[i][3];
        v1.x = oacc[i][4]; v1.y = oacc[i][5]; v1.z = oacc[i][6]; v1.w = oacc[i][7];
        *(float4*)(orow + (mr0 + i) * D + c0) = v0;
        *(float4*)(orow + (mr0 + i) * D + c1) = v1;
    }
}

extern "C" void kernel_launch(void* const* d_in, const int* in_sizes, int n_in,
                              void* d_out, int out_size)
{
    const float* features = (const float*)d_in[0];
    const float* W_pair   = (const float*)d_in[1];
    const float* b_pair   = (const float*)d_in[2];
    const float* W_final  = (const float*)d_in[3];
    const float* b_final  = (const float*)d_in[4];
    const int*   NAS      = (const int*)d_in[5];
    float*       out      = (float*)d_out;

    const int M = in_sizes[0] / (NFEAT * D);      // 16384 tokens
    const int grid = M / BM;                      // 256 blocks
    const size_t smem_bytes = (2 * (size_t)BM * D + 2 * KC * D) * sizeof(float); // 160 KB

    cudaFuncSetAttribute(cblock_kernel,
                         cudaFuncAttributeMaxDynamicSharedMemorySize,
                         (int)smem_bytes);
    cblock_kernel<<<grid, TPB, smem_bytes>>>(features, W_pair, b_pair,
                                             W_final, b_final, NAS, out, M);
}

// round 10
// speedup vs baseline: 1.0949x; 1.0401x over previous
#include <cuda_runtime.h>
#include <cuda_bf16.h>
#include <cstdint>

#define NFEAT  6
#define D      256
#define NPAIRS 15
#define BM     64
#define TPB    256
#define KC     16            // k-rows per pipelined chunk
#define NC     (D / KC)      // 16 chunks per 256-K GEMM

// triu_indices(6, k=1) pair order
__device__ __constant__ int cPI[NPAIRS] = {0,0,0,0,0,1,1,1,1,2,2,2,3,3,4};
__device__ __constant__ int cPJ[NPAIRS] = {1,2,3,4,5,2,3,4,5,3,4,5,4,5,5};

__device__ __forceinline__ void cp16(float* s, const float* g)
{
    unsigned int sa = (unsigned int)__cvta_generic_to_shared(s);
    asm volatile("cp.async.cg.shared.global [%0], [%1], 16;" :: "r"(sa), "l"(g));
}
#define CP_COMMIT() asm volatile("cp.async.commit_group;")
#define CP_WAIT0()  asm volatile("cp.async.wait_group 0;")

// packed f32x2 FMA: d = a*b + d (two independent fp32 FMAs, RN rounding)
__device__ __forceinline__ void fma2(unsigned long long& d,
                                     unsigned long long a,
                                     unsigned long long b)
{
    asm("fma.rn.f32x2 %0, %1, %2, %0;" : "+l"(d) : "l"(a), "l"(b));
}
// duplicate scalar into both halves of a 64-bit packed pair
__device__ __forceinline__ unsigned long long pack2(float x)
{
    unsigned long long r;
    unsigned int xb = __float_as_uint(x);
    asm("mov.b64 %0, {%1, %1};" : "=l"(r) : "r"(xb));
    return r;
}

// One 256-K GEMM: acc[8][4] (packed f32x2 pairs = 8 rows x 8 cols) +=
// Asm[64][256] @ wg[256][256]. cp.async double-buffered over 16-row W
// chunks; optionally stages Asm from gmem (ag) in the first cp.async group.
// Thread cols: pairs (c0,c0+1),(c0+2,c0+3),(c1..),(c1+2..) with c0=lane*4,
// c1=128+lane*4 -> warp B read = 512B contiguous, conflict-free.
__device__ __forceinline__ void gemm_stage(const float* __restrict__ Asm,
                                           const float* __restrict__ wg,
                                           float*       __restrict__ sWbuf,
                                           unsigned long long acc[8][4],
                                           int tid, int mr0, int lane,
                                           const float* __restrict__ ag)
{
    __syncthreads();                       // all warps done with prior sA/sW/sH use
    if (ag) {                              // stage A tile (64KB contiguous)
#pragma unroll
        for (int r = 0; r < 16; r++)
            cp16((float*)Asm + 4 * (tid + r * TPB), ag + 4 * (tid + r * TPB));
    }
#pragma unroll
    for (int r = 0; r < 4; r++)            // W chunk 0 -> buf0 (16KB)
        cp16(sWbuf + 4 * (tid + r * TPB), wg + 4 * (tid + r * TPB));
    CP_COMMIT();

#pragma unroll 1
    for (int kc = 0; kc < NC; kc++) {
        CP_WAIT0();
        __syncthreads();                   // chunk kc (and A) visible; prev compute done
        if (kc + 1 < NC) {                 // prefetch chunk kc+1, overlaps mma
            float*       nb = sWbuf + ((kc + 1) & 1) * (KC * D);
            const float* ng = wg + (size_t)(kc + 1) * KC * D;
#pragma unroll
            for (int r = 0; r < 4; r++)
                cp16(nb + 4 * (tid + r * TPB), ng + 4 * (tid + r * TPB));
            CP_COMMIT();
        }
        const float* Wc = sWbuf + (kc & 1) * (KC * D);
        const int kb = kc * KC;
#pragma unroll
        for (int kk = 0; kk < KC; kk += 4) {
            float a[8][4];
#pragma unroll
            for (int i = 0; i < 8; i++) {  // warp-broadcast A reads
                float4 t = *(const float4*)(Asm + (mr0 + i) * D + kb + kk);
                a[i][0] = t.x; a[i][1] = t.y; a[i][2] = t.z; a[i][3] = t.w;
            }
#pragma unroll
            for (int kj = 0; kj < 4; kj++) {
                const float* wr = Wc + (kk + kj) * D;
                ulonglong2 b01 = *(const ulonglong2*)(wr + lane * 4);
                ulonglong2 b23 = *(const ulonglong2*)(wr + 128 + lane * 4);
#pragma unroll
                for (int i = 0; i < 8; i++) {
                    unsigned long long ap = pack2(a[i][kj]);
                    fma2(acc[i][0], ap, b01.x);
                    fma2(acc[i][1], ap, b01.y);
                    fma2(acc[i][2], ap, b23.x);
                    fma2(acc[i][3], ap, b23.y);
                }
            }
        }
    }
}

__global__ void __launch_bounds__(TPB, 1)
cblock_kernel(const float* __restrict__ features,  // [6][M][256]
              const float* __restrict__ W_pair,    // [15][512][256]
              const float* __restrict__ b_pair,    // [15][256]
              const float* __restrict__ W_final,   // [3840][256]
              const float* __restrict__ b_final,   // [256]
              const int*   __restrict__ NAS,       // [6]
              float*       __restrict__ out,       // [M][256]
              int M)
{
    extern __shared__ float smem[];
    float* sA = smem;                       // 64 x 256  (feature tile, 64KB)
    float* sW = smem + BM * D;              // 2 x 16x256 (double-buffered W, 32KB)
    float* sH = smem + BM * D + 2 * KC * D; // 64 x 256  (tanh activations, 64KB)
    __shared__ float sMask[NPAIRS];
    __shared__ int   sNas[NFEAT];

    const int tid  = threadIdx.x;
    const int lane = tid & 31;
    const int wid  = tid >> 5;            // 8 warps, each owns 8 rows
    const int mr0  = wid * 8;
    const int c0   = lane * 4;
    const int c1   = 128 + lane * 4;
    const size_t m0 = (size_t)blockIdx.x * BM;

    if (tid < NFEAT) { int v = NAS[tid]; if (tid < 2) v = 1; sNas[tid] = v; }
    __syncthreads();
    if (tid < NPAIRS) sMask[tid] = (float)(sNas[cPI[tid]] * sNas[cPJ[tid]]);
    __syncthreads();

    // out accumulator (packed pairs), init with b_final
    unsigned long long oacc[8][4];
    {
        ulonglong2 f0 = *(const ulonglong2*)(b_final + c0);
        ulonglong2 f1 = *(const ulonglong2*)(b_final + c1);
#pragma unroll
        for (int i = 0; i < 8; i++) {
            oacc[i][0] = f0.x; oacc[i][1] = f0.y;
            oacc[i][2] = f1.x; oacc[i][3] = f1.y;
        }
    }

#pragma unroll 1
    for (int p = 0; p < NPAIRS; p++) {
        if (sMask[p] == 0.0f) continue;   // exact: masked pair contributes zero

        // h accumulator (packed pairs), init with b_pair[p]
        unsigned long long hacc[8][4];
        {
            ulonglong2 b0 = *(const ulonglong2*)(b_pair + p * D + c0);
            ulonglong2 b1 = *(const ulonglong2*)(b_pair + p * D + c1);
#pragma unroll
            for (int i = 0; i < 8; i++) {
                hacc[i][0] = b0.x; hacc[i][1] = b0.y;
                hacc[i][2] = b1.x; hacc[i][3] = b1.y;
            }
        }

        // Stage 1: hacc += f_i @ W_top  +  f_j @ W_bot
        {
            const int fi = cPI[p], fj = cPJ[p];
            gemm_stage(sA, W_pair + (size_t)p * 2 * D * D, sW, hacc,
                       tid, mr0, lane, features + ((size_t)fi * M + m0) * D);
            gemm_stage(sA, W_pair + ((size_t)p * 2 * D + D) * D, sW, hacc,
                       tid, mr0, lane, features + ((size_t)fj * M + m0) * D);
        }

        // tanh -> sH (stage2's internal barriers order writes before reads)
#pragma unroll
        for (int i = 0; i < 8; i++) {
            ulonglong2 s0, s1;
            {
                float2 v;
                v = *reinterpret_cast<float2*>(&hacc[i][0]);
                v.x = tanhf(v.x); v.y = tanhf(v.y);
                s0.x = *reinterpret_cast<unsigned long long*>(&v);
                v = *reinterpret_cast<float2*>(&hacc[i][1]);
                v.x = tanhf(v.x); v.y = tanhf(v.y);
                s0.y = *reinterpret_cast<unsigned long long*>(&v);
                v = *reinterpret_cast<float2*>(&hacc[i][2]);
                v.x = tanhf(v.x); v.y = tanhf(v.y);
                s1.x = *reinterpret_cast<unsigned long long*>(&v);
                v = *reinterpret_cast<float2*>(&hacc[i][3]);
                v.x = tanhf(v.x); v.y = tanhf(v.y);
                s1.y = *reinterpret_cast<unsigned long long*>(&v);
            }
            *(ulonglong2*)(sH + (mr0 + i) * D + c0) = s0;
            *(ulonglong2*)(sH + (mr0 + i) * D + c1) = s1;
        }

        // Stage 2: oacc += sH @ W_final[p*256:(p+1)*256, :]
        gemm_stage(sH, W_final + (size_t)p * D * D, sW, oacc,
                   tid, mr0, lane, (const float*)0);
    }

    // epilogue: coalesced 16B stores of packed pairs
    float* orow = out + m0 * D;
#pragma unroll
    for (int i = 0; i < 8; i++) {
        ulonglong2 v0, v1;
        v0.x = oacc[i][0]; v0.y = oacc[i][1];
        v1.x = oacc[i][2]; v1.y = oacc[i][3];
        *(ulonglong2*)(orow + (mr0 + i) * D + c0) = v0;
        *(ulonglong2*)(orow + (mr0 + i) * D + c1) = v1;
    }
}

extern "C" void kernel_launch(void* const* d_in, const int* in_sizes, int n_in,
                              void* d_out, int out_size)
{
    const float* features = (const float*)d_in[0];
    const float* W_pair   = (const float*)d_in[1];
    const float* b_pair   = (const float*)d_in[2];
    const float* W_final  = (const float*)d_in[3];
    const float* b_final  = (const float*)d_in[4];
    const int*   NAS      = (const int*)d_in[5];
    float*       out      = (float*)d_out;

    const int M = in_sizes[0] / (NFEAT * D);      // 16384 tokens
    const int grid = M / BM;                      // 256 blocks
    const size_t smem_bytes = (2 * (size_t)BM * D + 2 * KC * D) * sizeof(float); // 160 KB

    cudaFuncSetAttribute(cblock_kernel,
                         cudaFuncAttributeMaxDynamicSharedMemorySize,
                         (int)smem_bytes);
    cblock_kernel<<<grid, TPB, smem_bytes>>>(features, W_pair, b_pair,
                                             W_final, b_final, NAS, out, M);
}